// round 13
// baseline (speedup 1.0000x reference)
#include <cuda_runtime.h>
#include <cstdint>

// Spatial masked-pool-gate, single streaming pass — FINAL (converged).
//   xp = pad(x, 110->112); pooled = 4x4 sumpool(xp * mask);
//   out = (pooled > 0) ? xp : 0, cropped to 110x110.
//
// One thread per 4x4 patch; x read exactly once and register-held across
// pool->gate (traffic at the mandatory floor; measured DRAM bytes ~555 MB).
// Homogeneous float2 x/out accesses + float4 mask, default cache policy,
// 256 threads/block.
//
// Converged: 4 runs of this source give 87.6/87.7/88.1/89.0 us kernel at
// 79-80% DRAM-of-spec (the mixed-R/W HBM ceiling, best HBM 6358 GB/s).
// All explored alternatives (float4-even rows, streaming hints,
// 2 patches/thread, 512 TPB) measured neutral-to-worse. No unexplored
// lever with a positive predicted delta remains.

namespace {
constexpr int HIN  = 110;
constexpr int HPAD = 112;
constexpr int PP   = 28;               // patches per side (112/4)
constexpr int NCH  = 64 * 64;          // N*C channels
constexpr int CH_X = HIN * HIN;        // 12100 floats per channel (x/out)
constexpr int CH_M = HPAD * HPAD;      // 12544 floats per channel (mask)
}

__global__ __launch_bounds__(256)
void spatial_gate_kernel(const float* __restrict__ x,
                         const float* __restrict__ mask,
                         float* __restrict__ out)
{
    const int p  = blockIdx.x * 256 + threadIdx.x;   // exact grid, no guard
    const int pc = p % PP;
    const int t  = p / PP;
    const int pr = t % PP;
    const int ch = t / PP;

    const float* __restrict__ xc = x    + (size_t)ch * CH_X;
    const float* __restrict__ mc = mask + (size_t)ch * CH_M;
    float*       __restrict__ oc = out  + (size_t)ch * CH_X;

    const int c0 = pc * 4;
    const int r0 = pr * 4;
    const bool full_c = (c0 + 4 <= HIN);   // false only for pc == 27 (cols 108..111)

    float xv[4][4];
    float sum = 0.0f;

    #pragma unroll
    for (int i = 0; i < 4; ++i) {
        const int row = r0 + i;
        if (row < HIN) {
            const float*  xr = xc + row * HIN + c0;
            const float4  mv = *reinterpret_cast<const float4*>(mc + row * HPAD + c0);
            const float2  a  = *reinterpret_cast<const float2*>(xr);
            xv[i][0] = a.x; xv[i][1] = a.y;
            sum += a.x * mv.x;
            sum += a.y * mv.y;
            if (full_c) {
                const float2 b = *reinterpret_cast<const float2*>(xr + 2);
                xv[i][2] = b.x; xv[i][3] = b.y;
                sum += b.x * mv.z;
                sum += b.y * mv.w;
            }
        }
    }

    const float f = (sum > 0.0f) ? 1.0f : 0.0f;

    #pragma unroll
    for (int i = 0; i < 4; ++i) {
        const int row = r0 + i;
        if (row < HIN) {
            float* orow = oc + row * HIN + c0;
            float2 a;
            a.x = xv[i][0] * f;
            a.y = xv[i][1] * f;
            *reinterpret_cast<float2*>(orow) = a;
            if (full_c) {
                float2 b;
                b.x = xv[i][2] * f;
                b.y = xv[i][3] * f;
                *reinterpret_cast<float2*>(orow + 2) = b;
            }
        }
    }
}

extern "C" void kernel_launch(void* const* d_in, const int* in_sizes, int n_in,
                              void* d_out, int out_size)
{
    const float* x    = (const float*)d_in[0];
    const float* mask = (const float*)d_in[1];
    // d_in[2] is p_size (== 4), compile-time constant here.
    float* out = (float*)d_out;

    const int total_patches = NCH * PP * PP;       // 3,211,264
    const int blocks = total_patches / 256;        // 12,544 exact
    spatial_gate_kernel<<<blocks, 256>>>(x, mask, out);
}